// round 6
// baseline (speedup 1.0000x reference)
#include <cuda_runtime.h>
#include <cuda_bf16.h>
#include <cstdint>
#include <cstddef>

#define N_PTS 8192
#define DIMS  128
#define KNBR  14
#define NPAN  64                 // 64 panels of 128 rows
#define NPAIR 2080               // NPAN*(NPAN+1)/2 upper-tri tiles

#define SM_STRIDE 136            // bf16 row stride for A/B tiles
#define SC_STRIDE 129            // f32 score stride (conflict-light both directions)

// ---------------- scratch ----------------
__device__ __align__(16) __nv_bfloat16 g_XB[N_PTS * DIMS];   // 2 MB bf16 X (L2-resident)
__device__ float  g_SQ[N_PTS];
__device__ int    g_NBR[N_PTS * KNBR];
__device__ float  g_CK[(size_t)N_PTS * NPAN * KNBR];         // 29.4 MB candidate keys
__device__ int    g_CI[(size_t)N_PTS * NPAN * KNBR];         // 29.4 MB candidate idx
__device__ double g_partial_bulk[512];
__device__ double g_partial_corr[1024];

// ---------------- fast-math ----------------
__device__ __forceinline__ float f_sqrt(float x){ float r; asm("sqrt.approx.f32 %0, %1;" : "=f"(r) : "f"(x)); return r; }
__device__ __forceinline__ float f_rcp (float x){ float r; asm("rcp.approx.f32 %0, %1;"  : "=f"(r) : "f"(x)); return r; }
__device__ __forceinline__ float f_lg2 (float x){ float r; asm("lg2.approx.f32 %0, %1;"  : "=f"(r) : "f"(x)); return r; }
__device__ __forceinline__ float f_ex2 (float x){ float r; asm("ex2.approx.f32 %0, %1;"  : "=f"(r) : "f"(x)); return r; }

#define LN2F   0.69314718055994531f
#define LOG2EF 1.4426950408889634f

__device__ __forceinline__ void cp_async16(uint32_t dst, const void* src) {
    asm volatile("cp.async.cg.shared.global [%0], [%1], 16;" :: "r"(dst), "l"(src));
}
__device__ __forceinline__ void mma16816(float* c, const uint32_t* a, const uint32_t* b) {
    asm volatile(
        "mma.sync.aligned.m16n8k16.row.col.f32.bf16.bf16.f32 "
        "{%0,%1,%2,%3}, {%4,%5,%6,%7}, {%8,%9}, {%0,%1,%2,%3};"
        : "+f"(c[0]), "+f"(c[1]), "+f"(c[2]), "+f"(c[3])
        : "r"(a[0]), "r"(a[1]), "r"(a[2]), "r"(a[3]), "r"(b[0]), "r"(b[1]));
}

// ---------------- 1) prep ----------------
__global__ void prep_kernel(const float* __restrict__ X) {
    int warp = threadIdx.x >> 5, lane = threadIdx.x & 31;
    int row  = blockIdx.x * 8 + warp;
    const float* xr = X + (size_t)row * DIMS;
    float v0 = xr[lane], v1 = xr[lane + 32], v2 = xr[lane + 64], v3 = xr[lane + 96];
    __nv_bfloat16* xb = g_XB + (size_t)row * DIMS;
    xb[lane]      = __float2bfloat16(v0);
    xb[lane + 32] = __float2bfloat16(v1);
    xb[lane + 64] = __float2bfloat16(v2);
    xb[lane + 96] = __float2bfloat16(v3);
    float s = v0*v0 + v1*v1 + v2*v2 + v3*v3;
    #pragma unroll
    for (int off = 16; off; off >>= 1) s += __shfl_xor_sync(0xffffffffu, s, off);
    if (lane == 0) g_SQ[row] = s;
}

// ---------------- 2) symmetric fused GEMM + per-tile top-14 ----------------
// smem byte layout (dynamic, 99328 B total -> 2 blocks/SM):
//   [0, 34816)        sA 128x136 bf16          (score f32 128x129 aliases [0,66048))
//   [34816, 69632)    sB 128x136 bf16
//   [69632, 70144)    half-sq I panel (128 f32)
//   [70144, 70656)    half-sq J panel
//   [70656, 85 - )    stage keys 128*2*14 f32 = 14336
//   [84992?, ...)     stage idx  128*2*14 int = 14336
#define SMO_B   34816
#define SMO_SQI 69632
#define SMO_SQJ 70144
#define SMO_STK 70656
#define SMO_STI 84992
#define SM_TOT  99328

__global__ __launch_bounds__(256, 2) void fused_sym_gemm_topk() {
    extern __shared__ __align__(16) char smem[];
    __nv_bfloat16* sA   = (__nv_bfloat16*)smem;
    __nv_bfloat16* sB   = (__nv_bfloat16*)(smem + SMO_B);
    float*         sc   = (float*)smem;                 // aliases A/B after MMA
    float*         sqI  = (float*)(smem + SMO_SQI);
    float*         sqJ  = (float*)(smem + SMO_SQJ);
    float*         stK  = (float*)(smem + SMO_STK);
    int*           stI  = (int*)(smem + SMO_STI);
    uint32_t sA_u = (uint32_t)__cvta_generic_to_shared(sA);
    uint32_t sB_u = (uint32_t)__cvta_generic_to_shared(sB);

    int tid = threadIdx.x;

    // decode upper-tri pair (I <= J)
    int b = blockIdx.x;
    int I = (int)floorf(64.5f - f_sqrt(64.5f * 64.5f - 2.0f * (float)b));
    while (64 * (I + 1) - ((I + 1) * I) / 2 <= b) I++;
    while (64 * I - (I * (I - 1)) / 2 > b) I--;
    int J = I + (b - (64 * I - (I * (I - 1)) / 2));
    int Ibase = I * 128, Jbase = J * 128;

    // loads
    if (tid < 128) sqI[tid] = 0.5f * g_SQ[Ibase + tid];
    else           sqJ[tid - 128] = 0.5f * g_SQ[Jbase + tid - 128];
    #pragma unroll
    for (int i = 0; i < 8; i++) {
        int c = tid + i * 256;
        int r = c >> 4, q = (c & 15) * 8;
        cp_async16(sA_u + (uint32_t)(r * SM_STRIDE + q) * 2,
                   g_XB + (size_t)(Ibase + r) * DIMS + q);
    }
    #pragma unroll
    for (int i = 0; i < 8; i++) {
        int c = tid + i * 256;
        int r = c >> 4, q = (c & 15) * 8;
        cp_async16(sB_u + (uint32_t)(r * SM_STRIDE + q) * 2,
                   g_XB + (size_t)(Jbase + r) * DIMS + q);
    }
    asm volatile("cp.async.commit_group;");
    asm volatile("cp.async.wait_group 0;");
    __syncthreads();

    // ---- MMA: 128x128, warp grid 4x2, warp tile 32x64 ----
    int warp = tid >> 5, lane = tid & 31;
    int wm = warp & 3, wn = warp >> 2;
    int grp = lane >> 2, tig = lane & 3;

    float acc[2][8][4];
    #pragma unroll
    for (int mt = 0; mt < 2; mt++)
        #pragma unroll
        for (int nt = 0; nt < 8; nt++)
            #pragma unroll
            for (int q = 0; q < 4; q++) acc[mt][nt][q] = 0.f;

    const __nv_bfloat16* pA = sA + (wm * 32) * SM_STRIDE;
    const __nv_bfloat16* pB = sB + (wn * 64) * SM_STRIDE;

    #pragma unroll
    for (int kk = 0; kk < 8; kk++) {
        int kb = kk * 16;
        uint32_t afr[2][4];
        #pragma unroll
        for (int mt = 0; mt < 2; mt++) {
            const __nv_bfloat16* base = pA + (mt * 16 + grp) * SM_STRIDE + kb + tig * 2;
            afr[mt][0] = *(const uint32_t*)(base);
            afr[mt][1] = *(const uint32_t*)(base + 8 * SM_STRIDE);
            afr[mt][2] = *(const uint32_t*)(base + 8);
            afr[mt][3] = *(const uint32_t*)(base + 8 * SM_STRIDE + 8);
        }
        uint32_t bfr[8][2];
        #pragma unroll
        for (int nt = 0; nt < 8; nt++) {
            const __nv_bfloat16* base = pB + (nt * 8 + grp) * SM_STRIDE + kb + tig * 2;
            bfr[nt][0] = *(const uint32_t*)(base);
            bfr[nt][1] = *(const uint32_t*)(base + 8);
        }
        #pragma unroll
        for (int mt = 0; mt < 2; mt++)
            #pragma unroll
            for (int nt = 0; nt < 8; nt++)
                mma16816(acc[mt][nt], afr[mt], bfr[nt]);
    }
    __syncthreads();                       // all reads of sA/sB done before aliasing

    // ---- write raw dot scores to smem (aliases A/B) ----
    #pragma unroll
    for (int mt = 0; mt < 2; mt++) {
        #pragma unroll
        for (int nt = 0; nt < 8; nt++) {
            int lr = wm * 32 + mt * 16 + grp;
            int lc = wn * 64 + nt * 8 + tig * 2;
            sc[lr * SC_STRIDE + lc]           = acc[mt][nt][0];
            sc[lr * SC_STRIDE + lc + 1]       = acc[mt][nt][1];
            sc[(lr + 8) * SC_STRIDE + lc]     = acc[mt][nt][2];
            sc[(lr + 8) * SC_STRIDE + lc + 1] = acc[mt][nt][3];
        }
    }
    __syncthreads();

    // ---- scan 1 (rows of I over cols of J): 2 threads/row, 64 cols each ----
    {
        int r = tid >> 1, seg = tid & 1;
        float bk[KNBR]; int bi[KNBR];
        #pragma unroll
        for (int s = 0; s < KNBR; s++) { bk[s] = -3.4e38f; bi[s] = 0x7fffffff; }
        const float* prow = sc + r * SC_STRIDE + seg * 64;
        #pragma unroll 8
        for (int c = 0; c < 64; c++) {
            float key = prow[c] - sqJ[seg * 64 + c];
            if (key > bk[KNBR - 1]) {
                float cv = key; int ci = Jbase + seg * 64 + c;
                #pragma unroll
                for (int s = 0; s < KNBR; s++)
                    if (cv > bk[s]) { float tf = bk[s]; bk[s] = cv; cv = tf;
                                      int  ti = bi[s]; bi[s] = ci; ci = ti; }
            }
        }
        #pragma unroll
        for (int s = 0; s < KNBR; s++) { stK[tid * KNBR + s] = bk[s]; stI[tid * KNBR + s] = bi[s]; }
    }
    __syncthreads();
    if (tid < 128) {                       // 2-way merge -> slot J of row Ibase+tid
        const float* k0 = stK + (tid * 2) * KNBR;     const int* i0 = stI + (tid * 2) * KNBR;
        const float* k1 = stK + (tid * 2 + 1) * KNBR; const int* i1 = stI + (tid * 2 + 1) * KNBR;
        size_t base = ((size_t)(Ibase + tid) * NPAN + J) * KNBR;
        int p0 = 0, p1 = 0;
        #pragma unroll
        for (int s = 0; s < KNBR; s++) {
            float a = k0[p0], c = k1[p1];
            if (a >= c) { g_CK[base + s] = a; g_CI[base + s] = i0[p0]; p0++; }
            else        { g_CK[base + s] = c; g_CI[base + s] = i1[p1]; p1++; }
        }
    }

    if (I == J) return;                    // diagonal: row scan covered everything

    __syncthreads();                       // stage buffers free again
    // ---- scan 2 (rows of J over cols of I): column scan ----
    {
        int c = tid >> 1, seg = tid & 1;
        float bk[KNBR]; int bi[KNBR];
        #pragma unroll
        for (int s = 0; s < KNBR; s++) { bk[s] = -3.4e38f; bi[s] = 0x7fffffff; }
        const float* pcol = sc + (seg * 64) * SC_STRIDE + c;
        #pragma unroll 8
        for (int r = 0; r < 64; r++) {
            float key = pcol[r * SC_STRIDE] - sqI[seg * 64 + r];
            if (key > bk[KNBR - 1]) {
                float cv = key; int ci = Ibase + seg * 64 + r;
                #pragma unroll
                for (int s = 0; s < KNBR; s++)
                    if (cv > bk[s]) { float tf = bk[s]; bk[s] = cv; cv = tf;
                                      int  ti = bi[s]; bi[s] = ci; ci = ti; }
            }
        }
        #pragma unroll
        for (int s = 0; s < KNBR; s++) { stK[tid * KNBR + s] = bk[s]; stI[tid * KNBR + s] = bi[s]; }
    }
    __syncthreads();
    if (tid < 128) {                       // 2-way merge -> slot I of row Jbase+tid
        const float* k0 = stK + (tid * 2) * KNBR;     const int* i0 = stI + (tid * 2) * KNBR;
        const float* k1 = stK + (tid * 2 + 1) * KNBR; const int* i1 = stI + (tid * 2 + 1) * KNBR;
        size_t base = ((size_t)(Jbase + tid) * NPAN + I) * KNBR;
        int p0 = 0, p1 = 0;
        #pragma unroll
        for (int s = 0; s < KNBR; s++) {
            float a = k0[p0], c = k1[p1];
            if (a >= c) { g_CK[base + s] = a; g_CI[base + s] = i0[p0]; p0++; }
            else        { g_CK[base + s] = c; g_CI[base + s] = i1[p1]; p1++; }
        }
    }
}

// ---------------- 3) merge 64 candidate slots per row -> g_NBR ----------------
__global__ void merge_topk() {
    __shared__ float skey[8][32 * KNBR];
    __shared__ int   sidx[8][32 * KNBR];
    int warp = threadIdx.x >> 5, lane = threadIdx.x & 31;
    int row  = blockIdx.x * 8 + warp;

    float bk[KNBR]; int bi[KNBR];
    #pragma unroll
    for (int s = 0; s < KNBR; s++) { bk[s] = -3.4e38f; bi[s] = 0x7fffffff; }

    #pragma unroll
    for (int h = 0; h < 2; h++) {
        int slot = lane + h * 32;
        size_t base = ((size_t)row * NPAN + slot) * KNBR;
        #pragma unroll
        for (int s = 0; s < KNBR; s++) {
            float cv = g_CK[base + s];
            if (cv <= bk[KNBR - 1]) break;          // slot entries sorted desc
            int ci = g_CI[base + s];
            #pragma unroll
            for (int s2 = 0; s2 < KNBR; s2++)
                if (cv > bk[s2]) { float tf = bk[s2]; bk[s2] = cv; cv = tf;
                                   int  ti = bi[s2]; bi[s2] = ci; ci = ti; }
        }
    }
    #pragma unroll
    for (int s = 0; s < KNBR; s++) { skey[warp][lane * KNBR + s] = bk[s]; sidx[warp][lane * KNBR + s] = bi[s]; }
    __syncwarp();

    int p = 0;
    for (int r = 0; r < KNBR; r++) {
        float cand = (p < KNBR) ? skey[warp][lane * KNBR + p] : -3.4e38f;
        int   cidx = (p < KNBR) ? sidx[warp][lane * KNBR + p] : 0x7fffffff;
        int   owner = lane;
        #pragma unroll
        for (int off = 16; off; off >>= 1) {
            float ov = __shfl_xor_sync(0xffffffffu, cand, off);
            int   oi = __shfl_xor_sync(0xffffffffu, cidx, off);
            int   ow = __shfl_xor_sync(0xffffffffu, owner, off);
            if (ov > cand || (ov == cand && oi < cidx)) { cand = ov; cidx = oi; owner = ow; }
        }
        if (lane == owner) p++;
        if (lane == 0) g_NBR[row * KNBR + r] = cidx;
    }
}

// ---------------- 4) bulk lo-dim loss (triangular x2) ----------------
__global__ void bulk_kernel(const float* __restrict__ LO) {
    int ibase = blockIdx.x * 256, jbase = blockIdx.y * 512;
    if (jbase + 512 <= ibase) return;
    __shared__ float2 sLo[512];
    __shared__ double sred[256];
    int tid = threadIdx.x;
    const float2* lo2 = (const float2*)LO;
    int i = ibase + tid;
    float2 me = lo2[i];
    sLo[tid]       = lo2[jbase + tid];
    sLo[tid + 256] = lo2[jbase + 256 + tid];
    __syncthreads();

    float accf = 0.f;
    if (jbase >= ibase + 256) {
        #pragma unroll 4
        for (int j = 0; j < 512; j++) {
            float2 o = sLo[j];
            float dx = me.x - o.x, dy = me.y - o.y;
            float d  = f_sqrt(fmaf(dx, dx, dy * dy));
            float r  = f_rcp(1.0f + d);
            accf += f_lg2((1.0f - r) + 1e-10f);
        }
        accf *= 2.0f;
    } else {
        #pragma unroll 4
        for (int j = 0; j < 512; j++) {
            int jg = jbase + j;
            float2 o = sLo[j];
            float dx = me.x - o.x, dy = me.y - o.y;
            float d  = f_sqrt(fmaf(dx, dx, dy * dy));
            float r  = f_rcp(1.0f + d);
            float term = f_lg2((1.0f - r) + 1e-10f);
            float w = (jg > i) ? 2.0f : ((jg == i) ? 1.0f : 0.0f);
            accf += w * term;
        }
    }
    sred[tid] = (double)(accf * LN2F);
    __syncthreads();
    for (int off = 128; off; off >>= 1) { if (tid < off) sred[tid] += sred[tid + off]; __syncthreads(); }
    if (tid == 0) g_partial_bulk[blockIdx.y * 32 + blockIdx.x] = sred[0];
}

// ---------------- 5) exact neighbor correction ----------------
__global__ void corr_kernel(const float* __restrict__ X, const float* __restrict__ LO) {
    __shared__ double wsum[8];
    int warp = threadIdx.x >> 5, lane = threadIdx.x & 31;
    int row  = blockIdx.x * 8 + warp;
    const float* xi = X + (size_t)row * DIMS;
    float a0 = xi[lane], a1 = xi[lane + 32], a2 = xi[lane + 64], a3 = xi[lane + 96];
    const float2* lo2 = (const float2*)LO;
    float2 li = lo2[row];
    float sqi = g_SQ[row];

    float acc = 0.f;
    for (int n = 0; n < KNBR; n++) {
        int j = g_NBR[row * KNBR + n];
        const float* xj = X + (size_t)j * DIMS;
        float dot = a0 * xj[lane] + a1 * xj[lane + 32] + a2 * xj[lane + 64] + a3 * xj[lane + 96];
        #pragma unroll
        for (int off = 16; off; off >>= 1) dot += __shfl_xor_sync(0xffffffffu, dot, off);
        float d2h = fmaxf(sqi + g_SQ[j] - 2.f * dot, 0.f);
        float hd = f_sqrt(d2h);
        float hs = f_ex2(-LOG2EF * hd);
        float2 lj = lo2[j];
        float dx = li.x - lj.x, dy = li.y - lj.y;
        float ld = f_sqrt(fmaf(dx, dx, dy * dy));
        float r  = f_rcp(1.0f + ld);
        float A  = hs * (f_lg2(r + 1e-10f) * LN2F);
        float Bs = f_lg2((1.0f - r) + 1e-10f) * LN2F;
        acc += (A - Bs);
    }
    if (lane == 0) wsum[warp] = (double)acc;
    __syncthreads();
    if (threadIdx.x == 0) {
        double s = 0;
        for (int k = 0; k < 8; k++) s += wsum[k];
        g_partial_corr[blockIdx.x] = s;
    }
}

// ---------------- 6) deterministic final reduce ----------------
__global__ void final_kernel(float* __restrict__ out) {
    __shared__ double sred[256];
    int t = threadIdx.x;
    double s = 0;
    for (int k = t; k < 512;  k += 256) s += g_partial_bulk[k];
    for (int k = t; k < 1024; k += 256) s += g_partial_corr[k];
    sred[t] = s;
    __syncthreads();
    for (int off = 128; off; off >>= 1) { if (t < off) sred[t] += sred[t + off]; __syncthreads(); }
    if (t == 0) out[0] = (float)(-(sred[0] / 67108864.0) * 100.0);
}

// ---------------- launch ----------------
extern "C" void kernel_launch(void* const* d_in, const int* in_sizes, int n_in,
                              void* d_out, int out_size) {
    const float* X; const float* LO;
    if (in_sizes[0] == N_PTS * DIMS) { X = (const float*)d_in[0]; LO = (const float*)d_in[1]; }
    else                             { X = (const float*)d_in[1]; LO = (const float*)d_in[0]; }

    cudaFuncSetAttribute(fused_sym_gemm_topk, cudaFuncAttributeMaxDynamicSharedMemorySize, SM_TOT);

    prep_kernel        <<<N_PTS / 8, 256>>>(X);
    fused_sym_gemm_topk<<<NPAIR, 256, SM_TOT>>>();
    merge_topk         <<<N_PTS / 8, 256>>>();
    bulk_kernel        <<<dim3(32, 16), 256>>>(LO);
    corr_kernel        <<<N_PTS / 8, 256>>>(X, LO);
    final_kernel       <<<1, 256>>>((float*)d_out);
}